// round 2
// baseline (speedup 1.0000x reference)
#include <cuda_runtime.h>

// Problem constants
#define B_  2
#define H_  16
#define N_  2048
#define C_  1024
#define D_  64      // head dim
#define BM  64      // query tile
#define BN  64      // key tile

// scratch for attention output x in (B, C, N) layout
__device__ float g_x[B_ * C_ * N_];

// ---------------------------------------------------------------------------
// Kernel 1: fused attention (flash style), fp32.
// Grid: (N/BM, H, B), 256 threads. Per CTA: 64 query rows of one (b,h).
// q/k/v element (b,d,h,n) at b*2097152 + d*32768 + h*2048 + n.
// ---------------------------------------------------------------------------
__global__ void __launch_bounds__(256) attn_kernel(
    const float* __restrict__ q,
    const float* __restrict__ k,
    const float* __restrict__ v)
{
    extern __shared__ float smem[];
    float* Qs = smem;            // [64][64]  (d, n)
    float* Ks = Qs + 64 * 64;    // [64][64]  (d, m)
    float* Ps = Ks + 64 * 64;    // [64][64]  (n, m)
    float* Vt = Ps + 64 * 64;    // [64][68]  (m, d) transposed, padded
    const int VS = 68;

    const int b  = blockIdx.z;
    const int h  = blockIdx.y;
    const int n0 = blockIdx.x * BM;
    const int tid = threadIdx.x;
    const int tx = tid & 15;     // 0..15 -> 4 cols (m for S, d for O)
    const int ty = tid >> 4;     // 0..15 -> 4 rows (n)

    const float scale = 0.022097086912079608f;  // 1/sqrt(2048)
    const size_t base = (size_t)b * (C_ * N_) + (size_t)h * N_;
    const float* qb = q + base;
    const float* kb = k + base;
    const float* vb = v + base;

    // Load Q tile (prescaled)
    for (int idx = tid; idx < D_ * BM; idx += 256) {
        int d = idx >> 6, nl = idx & 63;
        Qs[d * 64 + nl] = qb[(size_t)d * (H_ * N_) + n0 + nl] * scale;
    }

    float o[4][4];
    float rmax[4], rsum[4];
#pragma unroll
    for (int i = 0; i < 4; i++) {
        rmax[i] = -1e30f;
        rsum[i] = 0.0f;
#pragma unroll
        for (int j = 0; j < 4; j++) o[i][j] = 0.0f;
    }

    for (int m0 = 0; m0 < N_; m0 += BN) {
        __syncthreads();  // protect Ks/Vt reuse across iterations (and Qs on iter 0)
        for (int idx = tid; idx < D_ * BN; idx += 256) {
            int d = idx >> 6, ml = idx & 63;
            float kv = kb[(size_t)d * (H_ * N_) + m0 + ml];
            float vv = vb[(size_t)d * (H_ * N_) + m0 + ml];
            Ks[d * 64 + ml] = kv;
            Vt[ml * VS + d] = vv;   // transposed store (padded stride)
        }
        __syncthreads();

        // S = Q^T K  (64x64), thread computes 4x4
        float s[4][4];
#pragma unroll
        for (int i = 0; i < 4; i++)
#pragma unroll
            for (int j = 0; j < 4; j++) s[i][j] = 0.0f;

#pragma unroll 8
        for (int d = 0; d < D_; d++) {
            float4 qv = *(const float4*)(Qs + d * 64 + ty * 4);
            float4 kv = *(const float4*)(Ks + d * 64 + tx * 4);
            float qa[4] = {qv.x, qv.y, qv.z, qv.w};
            float ka[4] = {kv.x, kv.y, kv.z, kv.w};
#pragma unroll
            for (int i = 0; i < 4; i++)
#pragma unroll
                for (int j = 0; j < 4; j++)
                    s[i][j] += qa[i] * ka[j];
        }

        // Online softmax, rows shared by the 16-lane tx group
#pragma unroll
        for (int i = 0; i < 4; i++) {
            float mx = fmaxf(fmaxf(s[i][0], s[i][1]), fmaxf(s[i][2], s[i][3]));
#pragma unroll
            for (int off = 8; off > 0; off >>= 1)
                mx = fmaxf(mx, __shfl_xor_sync(0xffffffffu, mx, off));
            float nm = fmaxf(rmax[i], mx);
            float corr = __expf(rmax[i] - nm);
            rmax[i] = nm;
            float sm = 0.0f;
#pragma unroll
            for (int j = 0; j < 4; j++) {
                float p = __expf(s[i][j] - nm);
                s[i][j] = p;
                sm += p;
            }
#pragma unroll
            for (int off = 8; off > 0; off >>= 1)
                sm += __shfl_xor_sync(0xffffffffu, sm, off);
            rsum[i] = rsum[i] * corr + sm;
#pragma unroll
            for (int j = 0; j < 4; j++) o[i][j] *= corr;
            float4 pv = make_float4(s[i][0], s[i][1], s[i][2], s[i][3]);
            *(float4*)(Ps + (ty * 4 + i) * 64 + tx * 4) = pv;
        }
        __syncthreads();  // Ps visible to all

        // O[n][d] += P[n][m] * Vt[m][d]
#pragma unroll 8
        for (int m = 0; m < BN; m++) {
            float4 vv = *(const float4*)(Vt + m * VS + tx * 4);
            float va[4] = {vv.x, vv.y, vv.z, vv.w};
            float p0 = Ps[(ty * 4 + 0) * 64 + m];
            float p1 = Ps[(ty * 4 + 1) * 64 + m];
            float p2 = Ps[(ty * 4 + 2) * 64 + m];
            float p3 = Ps[(ty * 4 + 3) * 64 + m];
#pragma unroll
            for (int j = 0; j < 4; j++) {
                o[0][j] += p0 * va[j];
                o[1][j] += p1 * va[j];
                o[2][j] += p2 * va[j];
                o[3][j] += p3 * va[j];
            }
        }
    }

    // Epilogue: x[b][(d*16+h)][n] = O[n][d] / rsum[n]
    float inv[4];
#pragma unroll
    for (int i = 0; i < 4; i++) inv[i] = 1.0f / rsum[i];

    float* xb = g_x + (size_t)b * (C_ * N_);
#pragma unroll
    for (int j = 0; j < 4; j++) {
        int d = tx * 4 + j;
        int c = d * H_ + h;
        float4 r = make_float4(o[0][j] * inv[0], o[1][j] * inv[1],
                               o[2][j] * inv[2], o[3][j] * inv[3]);
        *(float4*)(xb + (size_t)c * N_ + n0 + ty * 4) = r;  // n contiguous
    }
}

// ---------------------------------------------------------------------------
// Kernel 2: out[b][o][n] = bias[o] + sum_c W[o][c] * x[b][c][n]
// Tiled SGEMM 64x64, k-tile 16, 256 threads, 4x4 per thread.
// ---------------------------------------------------------------------------
__global__ void __launch_bounds__(256) merge_kernel(
    const float* __restrict__ W,
    const float* __restrict__ bias,
    float* __restrict__ out)
{
    __shared__ float Ws[16][68];   // [c][o] transposed, padded
    __shared__ float Xs[16][64];   // [c][n]

    const int b  = blockIdx.z;
    const int n0 = blockIdx.x * 64;
    const int o0 = blockIdx.y * 64;
    const int tid = threadIdx.x;
    const int tx = tid & 15;   // n
    const int ty = tid >> 4;   // o

    const float* xb = g_x + (size_t)b * (C_ * N_);

    float acc[4][4];
#pragma unroll
    for (int i = 0; i < 4; i++)
#pragma unroll
        for (int j = 0; j < 4; j++) acc[i][j] = 0.0f;

    for (int c0 = 0; c0 < C_; c0 += 16) {
        __syncthreads();
        for (int idx = tid; idx < 64 * 16; idx += 256) {
            int ol = idx >> 4, cl = idx & 15;
            Ws[cl][ol] = W[(size_t)(o0 + ol) * C_ + c0 + cl];
        }
        for (int idx = tid; idx < 16 * 64; idx += 256) {
            int cl = idx >> 6, nl = idx & 63;
            Xs[cl][nl] = xb[(size_t)(c0 + cl) * N_ + n0 + nl];
        }
        __syncthreads();

#pragma unroll
        for (int kk = 0; kk < 16; kk++) {
            float4 a  = *(const float4*)&Ws[kk][ty * 4];
            float4 bb = *(const float4*)&Xs[kk][tx * 4];
            float aa[4] = {a.x, a.y, a.z, a.w};
            float bv[4] = {bb.x, bb.y, bb.z, bb.w};
#pragma unroll
            for (int i = 0; i < 4; i++)
#pragma unroll
                for (int j = 0; j < 4; j++)
                    acc[i][j] += aa[i] * bv[j];
        }
    }

#pragma unroll
    for (int i = 0; i < 4; i++) {
        int oo = o0 + ty * 4 + i;
        float bv = bias[oo];
        float4 r = make_float4(acc[i][0] + bv, acc[i][1] + bv,
                               acc[i][2] + bv, acc[i][3] + bv);
        *(float4*)(out + (size_t)b * (C_ * N_) + (size_t)oo * N_ + n0 + tx * 4) = r;
    }
}

// ---------------------------------------------------------------------------
extern "C" void kernel_launch(void* const* d_in, const int* in_sizes, int n_in,
                              void* d_out, int out_size)
{
    const float* q    = (const float*)d_in[0];
    const float* k    = (const float*)d_in[1];
    const float* v    = (const float*)d_in[2];
    const float* W    = (const float*)d_in[3];
    const float* bias = (const float*)d_in[4];
    float* out = (float*)d_out;

    const int smem_attn = (3 * 64 * 64 + 64 * 68) * sizeof(float);  // 66560 B
    cudaFuncSetAttribute(attn_kernel, cudaFuncAttributeMaxDynamicSharedMemorySize, smem_attn);

    dim3 g1(N_ / BM, H_, B_);
    attn_kernel<<<g1, 256, smem_attn>>>(q, k, v);

    dim3 g2(N_ / 64, C_ / 64, B_);
    merge_kernel<<<g2, 256>>>(W, bias, out);
}

// round 3
// speedup vs baseline: 3.4574x; 3.4574x over previous
#include <cuda_runtime.h>
#include <stdint.h>

#define B_  2
#define H_  16
#define N_  2048
#define C_  1024
#define D_  64

// scratch: attention output x in (B, C, N) layout
__device__ float g_x[B_ * C_ * N_];

__device__ __forceinline__ uint32_t f2tf(float f) {
    uint32_t u;
    asm("cvt.rna.tf32.f32 %0, %1;" : "=r"(u) : "f"(f));
    return u;
}

__device__ __forceinline__ void mma8(float* c,
                                     uint32_t a0, uint32_t a1, uint32_t a2, uint32_t a3,
                                     uint32_t b0, uint32_t b1) {
    asm volatile(
        "mma.sync.aligned.m16n8k8.row.col.f32.tf32.tf32.f32 "
        "{%0,%1,%2,%3}, {%4,%5,%6,%7}, {%8,%9}, {%0,%1,%2,%3};"
        : "+f"(c[0]), "+f"(c[1]), "+f"(c[2]), "+f"(c[3])
        : "r"(a0), "r"(a1), "r"(a2), "r"(a3), "r"(b0), "r"(b1));
}

// ---------------------------------------------------------------------------
// Attention: CTA tile = 128 queries x all 2048 keys (64 per iter), tf32 MMA.
// grid (16, 16, 2), 256 threads (8 warps), warp owns 16 query rows.
// q/k/v element (b,d,h,n) at b*2097152 + d*32768 + h*2048 + n.
// smem (uint32): Qs[64][136] (d,n)  Ks[64][72] (d,m)  Vs[64][68] (d,m)
//                Ps[64][136] (m,n)
// ---------------------------------------------------------------------------
#define QS_OFF 0
#define KS_OFF 8704
#define VS_OFF 13312
#define PS_OFF 17664
#define SMEM_WORDS 26368

__global__ void __launch_bounds__(256, 2) attn_kernel(
    const float* __restrict__ q,
    const float* __restrict__ k,
    const float* __restrict__ v)
{
    extern __shared__ uint32_t sm[];
    uint32_t* Qs = sm + QS_OFF;
    uint32_t* Ks = sm + KS_OFF;
    uint32_t* Vs = sm + VS_OFF;
    uint32_t* Ps = sm + PS_OFF;

    const int b   = blockIdx.z;
    const int h   = blockIdx.y;
    const int n0q = blockIdx.x * 128;
    const int tid  = threadIdx.x;
    const int wid  = tid >> 5;
    const int lane = tid & 31;
    const int gid  = lane >> 2;   // 0..7
    const int tig  = lane & 3;    // 0..3
    const int nw   = wid * 16;    // warp row offset within 128

    const float scale = 0.022097086912079608f;  // 1/sqrt(2048)
    const size_t HN = (size_t)H_ * N_;
    const size_t base = (size_t)b * (C_ * N_) + (size_t)h * N_;
    const float* qb = q + base;
    const float* kb = k + base;
    const float* vb = v + base;

    // Load + convert Q tile (prescaled): 64 d-rows x 128 n-cols
    for (int i = tid; i < 64 * 32; i += 256) {
        int d = i >> 5, n4 = (i & 31) << 2;
        float4 t = *(const float4*)(qb + d * HN + n0q + n4);
        uint4 u = make_uint4(f2tf(t.x * scale), f2tf(t.y * scale),
                             f2tf(t.z * scale), f2tf(t.w * scale));
        *(uint4*)(Qs + d * 136 + n4) = u;
    }

    float o[8][4];
#pragma unroll
    for (int i = 0; i < 8; i++)
#pragma unroll
        for (int j = 0; j < 4; j++) o[i][j] = 0.0f;
    float rmax0 = -1e30f, rmax1 = -1e30f, rsum0 = 0.0f, rsum1 = 0.0f;

    for (int m0g = 0; m0g < N_; m0g += 64) {
        __syncthreads();  // prev PV reads done before overwriting Ks/Vs
        for (int i = tid; i < 64 * 16; i += 256) {
            int d = i >> 4, m4 = (i & 15) << 2;
            float4 tk = *(const float4*)(kb + d * HN + m0g + m4);
            float4 tv = *(const float4*)(vb + d * HN + m0g + m4);
            *(uint4*)(Ks + d * 72 + m4) =
                make_uint4(f2tf(tk.x), f2tf(tk.y), f2tf(tk.z), f2tf(tk.w));
            *(uint4*)(Vs + d * 68 + m4) =
                make_uint4(f2tf(tv.x), f2tf(tv.y), f2tf(tv.z), f2tf(tv.w));
        }
        __syncthreads();

        // ---- S = Q^T K : warp computes 16n x 64m ----
        float s[8][4];
#pragma unroll
        for (int mt = 0; mt < 8; mt++) {
            s[mt][0] = 0.f; s[mt][1] = 0.f; s[mt][2] = 0.f; s[mt][3] = 0.f;
        }
#pragma unroll
        for (int d0 = 0; d0 < 64; d0 += 8) {
            uint32_t a0 = Qs[(d0 + tig) * 136 + nw + gid];
            uint32_t a1 = Qs[(d0 + tig) * 136 + nw + gid + 8];
            uint32_t a2 = Qs[(d0 + tig + 4) * 136 + nw + gid];
            uint32_t a3 = Qs[(d0 + tig + 4) * 136 + nw + gid + 8];
#pragma unroll
            for (int mt = 0; mt < 8; mt++) {
                uint32_t b0 = Ks[(d0 + tig) * 72 + mt * 8 + gid];
                uint32_t b1 = Ks[(d0 + tig + 4) * 72 + mt * 8 + gid];
                mma8(s[mt], a0, a1, a2, a3, b0, b1);
            }
        }

        // ---- online softmax (rows gid and gid+8, warp-local) ----
        float mx0 = -1e30f, mx1 = -1e30f;
#pragma unroll
        for (int mt = 0; mt < 8; mt++) {
            mx0 = fmaxf(mx0, fmaxf(s[mt][0], s[mt][1]));
            mx1 = fmaxf(mx1, fmaxf(s[mt][2], s[mt][3]));
        }
        mx0 = fmaxf(mx0, __shfl_xor_sync(0xffffffffu, mx0, 1));
        mx0 = fmaxf(mx0, __shfl_xor_sync(0xffffffffu, mx0, 2));
        mx1 = fmaxf(mx1, __shfl_xor_sync(0xffffffffu, mx1, 1));
        mx1 = fmaxf(mx1, __shfl_xor_sync(0xffffffffu, mx1, 2));

        float nm0 = fmaxf(rmax0, mx0), nm1 = fmaxf(rmax1, mx1);
        float cr0 = __expf(rmax0 - nm0), cr1 = __expf(rmax1 - nm1);
        rmax0 = nm0; rmax1 = nm1;

        float sm0 = 0.0f, sm1 = 0.0f;
#pragma unroll
        for (int mt = 0; mt < 8; mt++) {
            float p0 = __expf(s[mt][0] - nm0);
            float p1 = __expf(s[mt][1] - nm0);
            float p2 = __expf(s[mt][2] - nm1);
            float p3 = __expf(s[mt][3] - nm1);
            sm0 += p0 + p1;
            sm1 += p2 + p3;
            int mrow = mt * 8 + 2 * tig;
            Ps[mrow * 136 + nw + gid]           = f2tf(p0);
            Ps[(mrow + 1) * 136 + nw + gid]     = f2tf(p1);
            Ps[mrow * 136 + nw + gid + 8]       = f2tf(p2);
            Ps[(mrow + 1) * 136 + nw + gid + 8] = f2tf(p3);
        }
        sm0 += __shfl_xor_sync(0xffffffffu, sm0, 1);
        sm0 += __shfl_xor_sync(0xffffffffu, sm0, 2);
        sm1 += __shfl_xor_sync(0xffffffffu, sm1, 1);
        sm1 += __shfl_xor_sync(0xffffffffu, sm1, 2);
        rsum0 = rsum0 * cr0 + sm0;
        rsum1 = rsum1 * cr1 + sm1;
#pragma unroll
        for (int dt = 0; dt < 8; dt++) {
            o[dt][0] *= cr0; o[dt][1] *= cr0;
            o[dt][2] *= cr1; o[dt][3] *= cr1;
        }
        __syncthreads();  // Ps visible to all warps

        // ---- O += P * V^T : warp 16n x 64d ----
#pragma unroll
        for (int m0 = 0; m0 < 64; m0 += 8) {
            uint32_t a0 = Ps[(m0 + tig) * 136 + nw + gid];
            uint32_t a1 = Ps[(m0 + tig) * 136 + nw + gid + 8];
            uint32_t a2 = Ps[(m0 + tig + 4) * 136 + nw + gid];
            uint32_t a3 = Ps[(m0 + tig + 4) * 136 + nw + gid + 8];
#pragma unroll
            for (int dt = 0; dt < 8; dt++) {
                uint32_t b0 = Vs[(dt * 8 + gid) * 68 + m0 + tig];
                uint32_t b1 = Vs[(dt * 8 + gid) * 68 + m0 + tig + 4];
                mma8(o[dt], a0, a1, a2, a3, b0, b1);
            }
        }
    }

    // epilogue: x[b][(d*16+h)][n] = O[n][d] / rsum
    float i0 = 1.0f / rsum0, i1 = 1.0f / rsum1;
    float* xb = g_x + (size_t)b * (C_ * N_);
    int ng0 = n0q + nw + gid;
    int ng1 = ng0 + 8;
#pragma unroll
    for (int dt = 0; dt < 8; dt++) {
        int d = dt * 8 + 2 * tig;
        int c = d * H_ + h;
        xb[(size_t)c * N_ + ng0]        = o[dt][0] * i0;
        xb[(size_t)(c + H_) * N_ + ng0] = o[dt][1] * i0;
        xb[(size_t)c * N_ + ng1]        = o[dt][2] * i1;
        xb[(size_t)(c + H_) * N_ + ng1] = o[dt][3] * i1;
    }
}

// ---------------------------------------------------------------------------
// Merge: out[b][o][n] = bias[o] + sum_c W[o][c] * x[b][c][n], tf32 MMA.
// grid (32, 8, 2), 256 threads; CTA tile 128o x 64n, k-tile 32.
// ---------------------------------------------------------------------------
__global__ void __launch_bounds__(256) merge_kernel(
    const float* __restrict__ W,
    const float* __restrict__ bias,
    float* __restrict__ out)
{
    __shared__ uint32_t Ws[32 * 136];  // (c, o)
    __shared__ uint32_t Xs[32 * 72];   // (c, n)

    const int b  = blockIdx.z;
    const int n0 = blockIdx.x * 64;
    const int o0 = blockIdx.y * 128;
    const int tid  = threadIdx.x;
    const int wid  = tid >> 5;
    const int lane = tid & 31;
    const int gid  = lane >> 2;
    const int tig  = lane & 3;
    const int ow   = wid * 16;

    const float* xb = g_x + (size_t)b * (C_ * N_);

    float acc[8][4];
#pragma unroll
    for (int i = 0; i < 8; i++)
#pragma unroll
        for (int j = 0; j < 4; j++) acc[i][j] = 0.0f;

    for (int c0 = 0; c0 < C_; c0 += 32) {
        __syncthreads();
        // W tile: 128 o-rows x 32 c, transposed store
        for (int i = tid; i < 128 * 8; i += 256) {
            int oo = i >> 3, c4 = (i & 7) << 2;
            float4 t = *(const float4*)(W + (size_t)(o0 + oo) * C_ + c0 + c4);
            Ws[(c4 + 0) * 136 + oo] = f2tf(t.x);
            Ws[(c4 + 1) * 136 + oo] = f2tf(t.y);
            Ws[(c4 + 2) * 136 + oo] = f2tf(t.z);
            Ws[(c4 + 3) * 136 + oo] = f2tf(t.w);
        }
        // X tile: 32 c-rows x 64 n
        for (int i = tid; i < 32 * 16; i += 256) {
            int cc = i >> 4, n4 = (i & 15) << 2;
            float4 t = *(const float4*)(xb + (size_t)(c0 + cc) * N_ + n0 + n4);
            *(uint4*)(Xs + cc * 72 + n4) =
                make_uint4(f2tf(t.x), f2tf(t.y), f2tf(t.z), f2tf(t.w));
        }
        __syncthreads();

#pragma unroll
        for (int kk = 0; kk < 32; kk += 8) {
            uint32_t a0 = Ws[(kk + tig) * 136 + ow + gid];
            uint32_t a1 = Ws[(kk + tig) * 136 + ow + gid + 8];
            uint32_t a2 = Ws[(kk + tig + 4) * 136 + ow + gid];
            uint32_t a3 = Ws[(kk + tig + 4) * 136 + ow + gid + 8];
#pragma unroll
            for (int nt = 0; nt < 8; nt++) {
                uint32_t b0 = Xs[(kk + tig) * 72 + nt * 8 + gid];
                uint32_t b1 = Xs[(kk + tig + 4) * 72 + nt * 8 + gid];
                mma8(acc[nt], a0, a1, a2, a3, b0, b1);
            }
        }
    }

    int og0 = o0 + ow + gid;
    int og1 = og0 + 8;
    float bv0 = bias[og0];
    float bv1 = bias[og1];
    float* ob = out + (size_t)b * (C_ * N_);
#pragma unroll
    for (int nt = 0; nt < 8; nt++) {
        int n = n0 + nt * 8 + 2 * tig;
        ob[(size_t)og0 * N_ + n]     = acc[nt][0] + bv0;
        ob[(size_t)og0 * N_ + n + 1] = acc[nt][1] + bv0;
        ob[(size_t)og1 * N_ + n]     = acc[nt][2] + bv1;
        ob[(size_t)og1 * N_ + n + 1] = acc[nt][3] + bv1;
    }
}

// ---------------------------------------------------------------------------
extern "C" void kernel_launch(void* const* d_in, const int* in_sizes, int n_in,
                              void* d_out, int out_size)
{
    const float* q    = (const float*)d_in[0];
    const float* k    = (const float*)d_in[1];
    const float* v    = (const float*)d_in[2];
    const float* W    = (const float*)d_in[3];
    const float* bias = (const float*)d_in[4];
    float* out = (float*)d_out;

    const int smem_attn = SMEM_WORDS * sizeof(uint32_t);  // 105472 B
    cudaFuncSetAttribute(attn_kernel, cudaFuncAttributeMaxDynamicSharedMemorySize, smem_attn);

    dim3 g1(N_ / 128, H_, B_);
    attn_kernel<<<g1, 256, smem_attn>>>(q, k, v);

    dim3 g2(N_ / 64, C_ / 128, B_);
    merge_kernel<<<g2, 256>>>(W, bias, out);
}

// round 5
// speedup vs baseline: 4.5120x; 1.3050x over previous
#include <cuda_runtime.h>
#include <stdint.h>

#define B_  2
#define H_  16
#define N_  2048
#define C_  1024
#define D_  64

// scratch: attention output x in (B, C, N) layout
__device__ float g_x[B_ * C_ * N_];

__device__ __forceinline__ uint32_t f2tf(float f) {
    uint32_t u;
    asm("cvt.rna.tf32.f32 %0, %1;" : "=r"(u) : "f"(f));
    return u;
}

__device__ __forceinline__ void mma8(float* c,
                                     uint32_t a0, uint32_t a1, uint32_t a2, uint32_t a3,
                                     uint32_t b0, uint32_t b1) {
    asm volatile(
        "mma.sync.aligned.m16n8k8.row.col.f32.tf32.tf32.f32 "
        "{%0,%1,%2,%3}, {%4,%5,%6,%7}, {%8,%9}, {%0,%1,%2,%3};"
        : "+f"(c[0]), "+f"(c[1]), "+f"(c[2]), "+f"(c[3])
        : "r"(a0), "r"(a1), "r"(a2), "r"(a3), "r"(b0), "r"(b1));
}

// ===========================================================================
// Attention: 4 warps / 128 threads per CTA. CTA tile 128 q x 64 k per iter.
// Warp owns 32 query rows = 2 subtiles of 16; B fragments shared across the
// two subtiles (1.5 smem wavefronts per mma instead of 2.5).
// smem (words): Qs[64][136] Ks[64][72] Vs[64][68] Ps[64][136]
// ===========================================================================
#define QS_OFF 0
#define KS_OFF 8704
#define VS_OFF 13312
#define PS_OFF 17664
#define SMEM_WORDS 26368

__global__ void __launch_bounds__(128, 2) attn_kernel(
    const float* __restrict__ q,
    const float* __restrict__ k,
    const float* __restrict__ v)
{
    extern __shared__ uint32_t sm[];
    uint32_t* Qs = sm + QS_OFF;
    uint32_t* Ks = sm + KS_OFF;
    uint32_t* Vs = sm + VS_OFF;
    uint32_t* Ps = sm + PS_OFF;

    const int b   = blockIdx.z;
    const int h   = blockIdx.y;
    const int n0q = blockIdx.x * 128;
    const int tid  = threadIdx.x;
    const int wid  = tid >> 5;
    const int lane = tid & 31;
    const int gid  = lane >> 2;   // 0..7
    const int tig  = lane & 3;    // 0..3
    const int nw   = wid * 32;    // warp covers rows nw..nw+31

    const float scale = 0.022097086912079608f;  // 1/sqrt(2048)
    const size_t HN = (size_t)H_ * N_;
    const size_t base = (size_t)b * (C_ * N_) + (size_t)h * N_;
    const float* qb = q + base;
    const float* kb = k + base;
    const float* vb = v + base;

    // Q tile: 64 d-rows x 128 n-cols, prescaled
    for (int i = tid; i < 64 * 32; i += 128) {
        int d = i >> 5, n4 = (i & 31) << 2;
        float4 t = *(const float4*)(qb + d * HN + n0q + n4);
        *(uint4*)(Qs + d * 136 + n4) =
            make_uint4(f2tf(t.x * scale), f2tf(t.y * scale),
                       f2tf(t.z * scale), f2tf(t.w * scale));
    }

    float o[2][8][4];
#pragma unroll
    for (int st = 0; st < 2; st++)
#pragma unroll
        for (int i = 0; i < 8; i++)
#pragma unroll
            for (int j = 0; j < 4; j++) o[st][i][j] = 0.0f;
    float rmax[2][2], rsum[2][2];
#pragma unroll
    for (int st = 0; st < 2; st++) {
        rmax[st][0] = -1e30f; rmax[st][1] = -1e30f;
        rsum[st][0] = 0.0f;   rsum[st][1] = 0.0f;
    }

    for (int m0g = 0; m0g < N_; m0g += 64) {
        __syncthreads();  // all warps done reading Ks/Vs from prev iter
        for (int i = tid; i < 64 * 16; i += 128) {
            int d = i >> 4, m4 = (i & 15) << 2;
            float4 tk = *(const float4*)(kb + d * HN + m0g + m4);
            float4 tv = *(const float4*)(vb + d * HN + m0g + m4);
            *(uint4*)(Ks + d * 72 + m4) =
                make_uint4(f2tf(tk.x), f2tf(tk.y), f2tf(tk.z), f2tf(tk.w));
            *(uint4*)(Vs + d * 68 + m4) =
                make_uint4(f2tf(tv.x), f2tf(tv.y), f2tf(tv.z), f2tf(tv.w));
        }
        __syncthreads();

        // ---- S = Q^T K : 2 subtiles (16n) x 64m, B frags shared ----
        float s[2][8][4];
#pragma unroll
        for (int st = 0; st < 2; st++)
#pragma unroll
            for (int mt = 0; mt < 8; mt++) {
                s[st][mt][0] = 0.f; s[st][mt][1] = 0.f;
                s[st][mt][2] = 0.f; s[st][mt][3] = 0.f;
            }
#pragma unroll
        for (int d0 = 0; d0 < 64; d0 += 8) {
            const uint32_t* r0 = Qs + (d0 + tig) * 136 + nw + gid;
            const uint32_t* r1 = Qs + (d0 + tig + 4) * 136 + nw + gid;
            uint32_t a00 = r0[0],  a01 = r0[8],  a02 = r1[0],  a03 = r1[8];
            uint32_t a10 = r0[16], a11 = r0[24], a12 = r1[16], a13 = r1[24];
#pragma unroll
            for (int mt = 0; mt < 8; mt++) {
                uint32_t b0 = Ks[(d0 + tig) * 72 + mt * 8 + gid];
                uint32_t b1 = Ks[(d0 + tig + 4) * 72 + mt * 8 + gid];
                mma8(s[0][mt], a00, a01, a02, a03, b0, b1);
                mma8(s[1][mt], a10, a11, a12, a13, b0, b1);
            }
        }

        // ---- online softmax per subtile ----
#pragma unroll
        for (int st = 0; st < 2; st++) {
            const int colb = nw + st * 16 + gid;
            float mx0 = -1e30f, mx1 = -1e30f;
#pragma unroll
            for (int mt = 0; mt < 8; mt++) {
                mx0 = fmaxf(mx0, fmaxf(s[st][mt][0], s[st][mt][1]));
                mx1 = fmaxf(mx1, fmaxf(s[st][mt][2], s[st][mt][3]));
            }
            mx0 = fmaxf(mx0, __shfl_xor_sync(0xffffffffu, mx0, 1));
            mx0 = fmaxf(mx0, __shfl_xor_sync(0xffffffffu, mx0, 2));
            mx1 = fmaxf(mx1, __shfl_xor_sync(0xffffffffu, mx1, 1));
            mx1 = fmaxf(mx1, __shfl_xor_sync(0xffffffffu, mx1, 2));

            float nm0 = fmaxf(rmax[st][0], mx0), nm1 = fmaxf(rmax[st][1], mx1);
            float cr0 = __expf(rmax[st][0] - nm0), cr1 = __expf(rmax[st][1] - nm1);
            rmax[st][0] = nm0; rmax[st][1] = nm1;

            float sm0 = 0.0f, sm1 = 0.0f;
#pragma unroll
            for (int mt = 0; mt < 8; mt++) {
                float p0 = __expf(s[st][mt][0] - nm0);
                float p1 = __expf(s[st][mt][1] - nm0);
                float p2 = __expf(s[st][mt][2] - nm1);
                float p3 = __expf(s[st][mt][3] - nm1);
                sm0 += p0 + p1;
                sm1 += p2 + p3;
                int mrow = mt * 8 + 2 * tig;
                Ps[mrow * 136 + colb]           = f2tf(p0);
                Ps[(mrow + 1) * 136 + colb]     = f2tf(p1);
                Ps[mrow * 136 + colb + 8]       = f2tf(p2);
                Ps[(mrow + 1) * 136 + colb + 8] = f2tf(p3);
            }
            sm0 += __shfl_xor_sync(0xffffffffu, sm0, 1);
            sm0 += __shfl_xor_sync(0xffffffffu, sm0, 2);
            sm1 += __shfl_xor_sync(0xffffffffu, sm1, 1);
            sm1 += __shfl_xor_sync(0xffffffffu, sm1, 2);
            rsum[st][0] = rsum[st][0] * cr0 + sm0;
            rsum[st][1] = rsum[st][1] * cr1 + sm1;
#pragma unroll
            for (int dt = 0; dt < 8; dt++) {
                o[st][dt][0] *= cr0; o[st][dt][1] *= cr0;
                o[st][dt][2] *= cr1; o[st][dt][3] *= cr1;
            }
        }
        __syncwarp();  // Ps is warp-local: warp-level visibility suffices

        // ---- O += P * V : 2 subtiles, V B-frags shared ----
#pragma unroll
        for (int m0 = 0; m0 < 64; m0 += 8) {
            const uint32_t* p0 = Ps + (m0 + tig) * 136 + nw + gid;
            const uint32_t* p1 = Ps + (m0 + tig + 4) * 136 + nw + gid;
            uint32_t a00 = p0[0],  a01 = p0[8],  a02 = p1[0],  a03 = p1[8];
            uint32_t a10 = p0[16], a11 = p0[24], a12 = p1[16], a13 = p1[24];
#pragma unroll
            for (int dt = 0; dt < 8; dt++) {
                uint32_t b0 = Vs[(dt * 8 + gid) * 68 + m0 + tig];
                uint32_t b1 = Vs[(dt * 8 + gid) * 68 + m0 + tig + 4];
                mma8(o[0][dt], a00, a01, a02, a03, b0, b1);
                mma8(o[1][dt], a10, a11, a12, a13, b0, b1);
            }
        }
    }

    // epilogue: x[b][(d*16+h)][n] = O[n][d] / rsum
    float* xb = g_x + (size_t)b * (C_ * N_);
#pragma unroll
    for (int st = 0; st < 2; st++) {
        float i0 = 1.0f / rsum[st][0], i1 = 1.0f / rsum[st][1];
        int ng0 = n0q + nw + st * 16 + gid;
        int ng1 = ng0 + 8;
#pragma unroll
        for (int dt = 0; dt < 8; dt++) {
            int d = dt * 8 + 2 * tig;
            int c = d * H_ + h;
            xb[(size_t)c * N_ + ng0]        = o[st][dt][0] * i0;
            xb[(size_t)(c + H_) * N_ + ng0] = o[st][dt][1] * i0;
            xb[(size_t)c * N_ + ng1]        = o[st][dt][2] * i1;
            xb[(size_t)(c + H_) * N_ + ng1] = o[st][dt][3] * i1;
        }
    }
}

// ===========================================================================
// Merge: out[b][o][n] = bias[o] + sum_c W[o][c] * x[b][c][n].
// 8 warps, CTA tile 128o x 128n, k-chunk 32. Fragment-major smem layout:
// conflict-free vectorized STS + single LDS.128/LDS.64 per fragment.
// Warp tile 32o x 64n (2 o-subtiles share every B fragment).
// ===========================================================================
__global__ void __launch_bounds__(256, 2) merge_kernel(
    const float* __restrict__ W,
    const float* __restrict__ bias,
    float* __restrict__ out)
{
    // Wf: [kk8(4)][osub(8)][lane(32)][4 words]   = 4096 words
    // Xf: [kk8(4)][nt(16)][lane(32)][2 words]    = 4096 words
    __shared__ uint32_t Wf[4096];
    __shared__ uint32_t Xf[4096];

    const int b  = blockIdx.z;
    const int n0 = blockIdx.x * 128;
    const int o0 = blockIdx.y * 128;
    const int tid  = threadIdx.x;
    const int wid  = tid >> 5;
    const int lane = tid & 31;
    const int wo   = wid >> 1;   // 0..3 : o-position (32 rows)
    const int wn   = wid & 1;    // 0..1 : n-half (64 cols)

    const float* xb = g_x + (size_t)b * (C_ * N_);

    float acc[2][8][4];
#pragma unroll
    for (int st = 0; st < 2; st++)
#pragma unroll
        for (int i = 0; i < 8; i++)
#pragma unroll
            for (int j = 0; j < 4; j++) acc[st][i][j] = 0.0f;

    for (int c0 = 0; c0 < C_; c0 += 32) {
        __syncthreads();
        // --- stage W fragments: 1024 frag-lanes, 4 scalars each ---
#pragma unroll
        for (int t = 0; t < 4; t++) {
            int fl = tid + t * 256;
            int kk8  = fl >> 8;
            int osub = (fl >> 5) & 7;
            int ln   = fl & 31;
            int r = ln >> 2, tg = ln & 3;
            const float* wp = W + (size_t)(o0 + osub * 16 + r) * C_ + c0 + kk8 * 8 + tg;
            float w0 = wp[0];
            float w1 = wp[8 * C_];
            float w2 = wp[4];
            float w3 = wp[8 * C_ + 4];
            *(uint4*)(Wf + fl * 4) =
                make_uint4(f2tf(w0), f2tf(w1), f2tf(w2), f2tf(w3));
        }
        // --- stage X fragments: 2048 frag-lanes, 2 scalars each ---
#pragma unroll
        for (int t = 0; t < 8; t++) {
            int fl = tid + t * 256;
            int kk8 = fl >> 9;
            int nt  = (fl >> 5) & 15;
            int ln  = fl & 31;
            int gd = ln >> 2, tg = ln & 3;
            const float* xp = xb + (size_t)(c0 + kk8 * 8 + tg) * N_ + n0 + nt * 8 + gd;
            float x0 = xp[0];
            float x1 = xp[4 * N_];
            *(uint2*)(Xf + fl * 2) = make_uint2(f2tf(x0), f2tf(x1));
        }
        __syncthreads();

#pragma unroll
        for (int kk8 = 0; kk8 < 4; kk8++) {
            uint4 A0 = *(const uint4*)(Wf + ((kk8 * 8 + wo * 2 + 0) * 32 + lane) * 4);
            uint4 A1 = *(const uint4*)(Wf + ((kk8 * 8 + wo * 2 + 1) * 32 + lane) * 4);
#pragma unroll
            for (int nt = 0; nt < 8; nt++) {
                uint2 Bv = *(const uint2*)(Xf + ((kk8 * 16 + wn * 8 + nt) * 32 + lane) * 2);
                mma8(acc[0][nt], A0.x, A0.y, A0.z, A0.w, Bv.x, Bv.y);
                mma8(acc[1][nt], A1.x, A1.y, A1.z, A1.w, Bv.x, Bv.y);
            }
        }
    }

    const int gid = lane >> 2, tig = lane & 3;
    float* ob = out + (size_t)b * (C_ * N_);
#pragma unroll
    for (int st = 0; st < 2; st++) {
        int og0 = o0 + wo * 32 + st * 16 + gid;
        int og1 = og0 + 8;
        float bv0 = bias[og0];
        float bv1 = bias[og1];
#pragma unroll
        for (int nt = 0; nt < 8; nt++) {
            int n = n0 + wn * 64 + nt * 8 + 2 * tig;
            *(float2*)(ob + (size_t)og0 * N_ + n) =
                make_float2(acc[st][nt][0] + bv0, acc[st][nt][1] + bv0);
            *(float2*)(ob + (size_t)og1 * N_ + n) =
                make_float2(acc[st][nt][2] + bv1, acc[st][nt][3] + bv1);
        }
    }
}

// ---------------------------------------------------------------------------
extern "C" void kernel_launch(void* const* d_in, const int* in_sizes, int n_in,
                              void* d_out, int out_size)
{
    const float* q    = (const float*)d_in[0];
    const float* k    = (const float*)d_in[1];
    const float* v    = (const float*)d_in[2];
    const float* W    = (const float*)d_in[3];
    const float* bias = (const float*)d_in[4];
    float* out = (float*)d_out;

    const int smem_attn = SMEM_WORDS * sizeof(uint32_t);  // 105472 B
    cudaFuncSetAttribute(attn_kernel, cudaFuncAttributeMaxDynamicSharedMemorySize, smem_attn);

    dim3 g1(N_ / 128, H_, B_);
    attn_kernel<<<g1, 128, smem_attn>>>(q, k, v);

    dim3 g2(N_ / 128, C_ / 128, B_);
    merge_kernel<<<g2, 256>>>(W, bias, out);
}